// round 16
// baseline (speedup 1.0000x reference)
#include <cuda_runtime.h>
#include <cuda_bf16.h>
#include <math.h>

#define N_NODES 1024
#define KNB 16
#define CZ 128
#define CG 16
#define CS 256
#define NRBF 64
#define TRI_GRID 296   // 2 CTAs x 148 SMs, persistent

// scratch (no cudaMalloc allowed)
__device__ float g_nl[N_NODES * CG];
__device__ float g_nr[N_NODES * CG];
__device__ float g_tt[N_NODES * CG * CZ];   // TT[s][p][c] — coalesced across c

__device__ __forceinline__ float sigmoidf_(float x) {
    return 1.0f / (1.0f + __expf(-x));
}

// --- input-encoding sniffers ---
__device__ __forceinline__ bool eidx_is_i64(const void* e) {
    const long long* e64 = (const long long*)e;
    bool is64 = true;
#pragma unroll
    for (int i = 0; i < 4; i++)
        if ((unsigned long long)e64[i] >= 1024ull) is64 = false;
    return is64;
}
__device__ __forceinline__ int load_idx(const void* e, bool is64, int idx) {
    return is64 ? (int)((const long long*)e)[idx] : ((const int*)e)[idx];
}
__device__ __forceinline__ bool mask_true(const void* rm, int s) {
    const unsigned int w0 = ((const unsigned int*)rm)[0];
    const unsigned int w1 = ((const unsigned int*)rm)[1];
    if (w0 == 0x3F800000u) return ((const float*)rm)[s] != 0.0f;
    if ((w0 & 0xFFFFFF00u) != 0u) return ((const unsigned char*)rm)[s] != 0;
    const unsigned int w3 = ((const unsigned int*)rm)[3];
    if (w1 == 0u && w3 == 0u) return ((const long long*)rm)[s] != 0;
    return ((const int*)rm)[s] != 0;
}

// nl = nf @ Wl + bl ; nr = nf @ Wr + br
__global__ __launch_bounds__(256)
void node_proj_kernel(const float* __restrict__ nf,
                      const float* __restrict__ Wl, const float* __restrict__ bl,
                      const float* __restrict__ Wr, const float* __restrict__ br) {
    __shared__ float x[CS];
    const int n = blockIdx.x, t = threadIdx.x;
    x[t] = nf[n * CS + t];
    __syncthreads();
    const int o = t >> 3, l8 = t & 7;
    const int cc = o & 15, sel = o >> 4;
    const float* W = sel ? Wr : Wl;
    float s = 0.f;
    for (int i = l8; i < CS; i += 8) s += x[i] * W[i * CG + cc];
#pragma unroll
    for (int off = 4; off; off >>= 1) s += __shfl_down_sync(0xffffffffu, s, off, 8);
    if (l8 == 0) {
        float bias = sel ? br[cc] : bl[cc];
        (sel ? g_nr : g_nl)[n * CG + cc] = s + bias;
    }
}

// TT[s][p][c] = sum_q nr[s][q] * Wdg[(p*16+q)][c]
__global__ __launch_bounds__(256)
void tt_kernel(const float* __restrict__ Wdg) {
    __shared__ float bq[CG];
    const int s = blockIdx.x, t = threadIdx.x;
    if (t < CG) bq[t] = g_nr[s * CG + t];
    __syncthreads();
    const int c = t & 127, ph = t >> 7;
    float bl_[CG];
#pragma unroll
    for (int q = 0; q < CG; q++) bl_[q] = bq[q];
#pragma unroll
    for (int pp = 0; pp < 8; pp++) {
        int p = ph * 8 + pp;
        float acc = 0.f;
#pragma unroll
        for (int q = 0; q < CG; q++)
            acc += bl_[q] * Wdg[(p * CG + q) * CZ + c];
        g_tt[((size_t)s * CG + p) * CZ + c] = acc;
    }
}

// u48 arena (48KB = 12288 floats), phase-multiplexed:
//   e2 phase:      2 x 24KB (6144 floats) weight chunk buffers {P:0, G:+2048, O:+4096}
//   contraction:   TT planes at [0,2048),[2048,4096); RBF table at [4096,6144)
//   wout phase:    2 x 8KB (2048 floats) weight chunks at [0,2048),[2048,4096)
struct __align__(16) TriSmem {
    float zu[KNB][CZ];      // 8KB: z (LN'd), later upd
    float e2s[KNB][CZ];     // 8KB
    float wdp[NRBF][CZ];    // 32KB Wdp table
    float u48[12288];       // 48KB arena
    int   r0[256];
    float a[KNB][CG];
    float tp[KNB][4];
    int   src[KNB];
    float mk[KNB];
};

// 512 threads, persistent: thread (c, g) owns 4 output rows jb=g*4 .. jb+3
__global__ __launch_bounds__(512, 2)
void tri_kernel(const float* __restrict__ trans,
                const float* __restrict__ ef,
                const float* __restrict__ ln_g,  const float* __restrict__ ln_b,
                const float* __restrict__ Wep,   const float* __restrict__ bep,
                const float* __restrict__ Weg,   const float* __restrict__ beg,
                const float* __restrict__ bdg,
                const float* __restrict__ Wdp,   const float* __restrict__ bdp,
                const float* __restrict__ lno_g, const float* __restrict__ lno_b,
                const float* __restrict__ Wout,  const float* __restrict__ bout,
                const float* __restrict__ Wog,   const float* __restrict__ bog,
                const void* __restrict__ eidx,
                const void* __restrict__ res_mask,
                float* __restrict__ out) {
    extern __shared__ char smem_raw[];
    TriSmem& sm = *reinterpret_cast<TriSmem*>(smem_raw);

    const int t = threadIdx.x;
    const int lane = t & 31, w = t >> 5;   // 16 warps
    const int c = t & 127, g = t >> 7;     // g in [0,4)
    const int jb = g * 4;
    const int wr = t >> 5;                 // weight-chunk row for this thread
    const int wc4 = (t & 31) * 4;          // weight-chunk float4 column
    const bool is64 = eidx_is_i64(eidx);

    // Wdp -> smem, once per CTA
    {
        const float4* src4 = reinterpret_cast<const float4*>(Wdp);
        float4* dst4 = reinterpret_cast<float4*>(&sm.wdp[0][0]);
#pragma unroll
        for (int i = 0; i < 4; i++) dst4[t + 512 * i] = src4[t + 512 * i];
    }

    for (int n = blockIdx.x; n < N_NODES; n += TRI_GRID) {
        __syncthreads();   // protect smem reuse across node iterations

        if (t < KNB) {
            int s = load_idx(eidx, is64, n * KNB + t);
            sm.src[t] = s;
            sm.mk[t] = (mask_true(res_mask, s) && mask_true(res_mask, n)) ? 1.f : 0.f;
        }
        __syncthreads();

        // a = nl[src], neighbor positions (first 256 threads)
        if (t < 256) {
            int k = t >> 4, p = t & 15;
            int s = sm.src[k];
            sm.a[k][p] = g_nl[s * CG + p];
            if (p < 3) sm.tp[k][p] = trans[s * 3 + p];
        }

        // early prefetches, hidden under LN: TT plane k=0 + e2 weight chunk 0
        float4 pf = reinterpret_cast<const float4*>(
            &g_tt[(size_t)sm.src[0] * (CG * CZ)])[t];
        float4 pwp = *reinterpret_cast<const float4*>(&Wep[wr * CZ + wc4]);
        float4 pwg = *reinterpret_cast<const float4*>(&Weg[wr * CZ + wc4]);
        float4 pwo = *reinterpret_cast<const float4*>(&Wog[wr * CZ + wc4]);

        // z = LayerNorm(edge rows): warp w -> row w
        {
            const float* row = ef + ((size_t)n * KNB + w) * CZ;
            float v[4];
#pragma unroll
            for (int i = 0; i < 4; i++) v[i] = row[lane + 32 * i];
            float s = v[0] + v[1] + v[2] + v[3];
            float ss = v[0] * v[0] + v[1] * v[1] + v[2] * v[2] + v[3] * v[3];
#pragma unroll
            for (int off = 16; off; off >>= 1) {
                s  += __shfl_xor_sync(0xffffffffu, s, off);
                ss += __shfl_xor_sync(0xffffffffu, ss, off);
            }
            float m = s * (1.f / 128.f);
            float var = ss * (1.f / 128.f) - m * m;
            float inv = rsqrtf(var + 1e-5f);
#pragma unroll
            for (int i = 0; i < 4; i++) {
                int cc = lane + 32 * i;
                sm.zu[w][cc] = (v[i] - m) * inv * ln_g[cc] + ln_b[cc];
            }
        }
        __syncthreads();

        // e2 = sigmoid(z@Weg+beg)*(z@Wep+bep) (mk folded); gz kept in regs
        // weights staged through u48 double buffer, prefetched 1 chunk ahead
        float gzr[4];
        {
            float aP[4] = {0.f, 0.f, 0.f, 0.f};
            float aG[4] = {0.f, 0.f, 0.f, 0.f};
            float aO[4] = {0.f, 0.f, 0.f, 0.f};
#pragma unroll 1
            for (int ci = 0; ci < 8; ci++) {
                float* wbP = sm.u48 + (ci & 1) * 6144;
                float* wbG = wbP + 2048;
                float* wbO = wbP + 4096;
                reinterpret_cast<float4*>(wbP)[t] = pwp;
                reinterpret_cast<float4*>(wbG)[t] = pwg;
                reinterpret_cast<float4*>(wbO)[t] = pwo;
                __syncthreads();
                if (ci < 7) {
                    int r = (ci + 1) * 16 + wr;
                    pwp = *reinterpret_cast<const float4*>(&Wep[r * CZ + wc4]);
                    pwg = *reinterpret_cast<const float4*>(&Weg[r * CZ + wc4]);
                    pwo = *reinterpret_cast<const float4*>(&Wog[r * CZ + wc4]);
                }
#pragma unroll
                for (int ii = 0; ii < 16; ii += 4) {
                    float wp0 = wbP[(ii + 0) * CZ + c], wp1 = wbP[(ii + 1) * CZ + c];
                    float wp2 = wbP[(ii + 2) * CZ + c], wp3 = wbP[(ii + 3) * CZ + c];
                    float wg0 = wbG[(ii + 0) * CZ + c], wg1 = wbG[(ii + 1) * CZ + c];
                    float wg2 = wbG[(ii + 2) * CZ + c], wg3 = wbG[(ii + 3) * CZ + c];
                    float wo0 = wbO[(ii + 0) * CZ + c], wo1 = wbO[(ii + 1) * CZ + c];
                    float wo2 = wbO[(ii + 2) * CZ + c], wo3 = wbO[(ii + 3) * CZ + c];
                    const int ib = ci * 16 + ii;
#pragma unroll
                    for (int jj = 0; jj < 4; jj++) {
                        float4 z4 = *reinterpret_cast<const float4*>(&sm.zu[jb + jj][ib]);
                        aP[jj] += z4.x * wp0 + z4.y * wp1 + z4.z * wp2 + z4.w * wp3;
                        aG[jj] += z4.x * wg0 + z4.y * wg1 + z4.z * wg2 + z4.w * wg3;
                        aO[jj] += z4.x * wo0 + z4.y * wo1 + z4.z * wo2 + z4.w * wo3;
                    }
                }
            }
            float bp = bep[c], bg = beg[c], bo = bog[c];
#pragma unroll
            for (int jj = 0; jj < 4; jj++) {
                int k = jb + jj;
                sm.e2s[k][c] = sigmoidf_(aG[jj] + bg) * (aP[jj] + bp) * sm.mk[k];
                gzr[jj] = sigmoidf_(aO[jj] + bo);
            }
        }

        // RBF windows per pair (first 256 threads), 8 taps
        // rbf table at u48[4096..6144) — lower half; last e2 chunk used upper half,
        // so no write-read race (all e2 reads of lower half ended before bar(ci=7)).
        if (t < 256) {
            int j = t >> 4, k = t & 15;
            float dx = sm.tp[j][0] - sm.tp[k][0] + 1e-8f;
            float dy = sm.tp[j][1] - sm.tp[k][1] + 1e-8f;
            float dz = sm.tp[j][2] - sm.tp[k][2] + 1e-8f;
            float d = sqrtf(dx * dx + dy * dy + dz * dz);
            const float STEP = 20.f / 63.f;
            const float INVS = 1.f / 0.3125f;
            int r0 = (int)floorf(d * (63.f / 20.f)) - 3;
            r0 = r0 < 0 ? 0 : (r0 > 56 ? 56 : r0);
            float* rb = sm.u48 + 4096 + t * 8;
#pragma unroll
            for (int i = 0; i < 8; i++) {
                float mu = (float)(r0 + i) * STEP;
                float x = (d - mu) * INVS;
                rb[i] = __expf(-x * x);
            }
            sm.r0[t] = r0;
        }
        __syncthreads();

        // contraction: TT staged via u48[0..4096) double buffer, 1 barrier per k
        float updp[4] = {0.f, 0.f, 0.f, 0.f};
        const float bdgc = bdg[c], bdpc = bdp[c];

#pragma unroll 1
        for (int k = 0; k < 16; k++) {
            float* buf = sm.u48 + (k & 1) * 2048;
            reinterpret_cast<float4*>(buf)[t] = pf;
            __syncthreads();
            if (k < 15) {
                pf = reinterpret_cast<const float4*>(
                    &g_tt[(size_t)sm.src[k + 1] * (CG * CZ)])[t];
            }
            float ttc[16];
#pragma unroll
            for (int p = 0; p < 16; p++) ttc[p] = buf[p * CZ + c];
            const float e2k = sm.e2s[k][c];
#pragma unroll
            for (int jj = 0; jj < 4; jj++) {
                const int j = jb + jj;
                float4 a0 = *reinterpret_cast<const float4*>(&sm.a[j][0]);
                float4 a1 = *reinterpret_cast<const float4*>(&sm.a[j][4]);
                float4 a2 = *reinterpret_cast<const float4*>(&sm.a[j][8]);
                float4 a3 = *reinterpret_cast<const float4*>(&sm.a[j][12]);
                float gate = bdgc
                    + a0.x * ttc[0]  + a0.y * ttc[1]  + a0.z * ttc[2]  + a0.w * ttc[3]
                    + a1.x * ttc[4]  + a1.y * ttc[5]  + a1.z * ttc[6]  + a1.w * ttc[7]
                    + a2.x * ttc[8]  + a2.y * ttc[9]  + a2.z * ttc[10] + a2.w * ttc[11]
                    + a3.x * ttc[12] + a3.y * ttc[13] + a3.z * ttc[14] + a3.w * ttc[15];
                const int pr = j * 16 + k;
                const float* rb = sm.u48 + 4096 + pr * 8;
                float4 rv0 = *reinterpret_cast<const float4*>(&rb[0]);
                float4 rv1 = *reinterpret_cast<const float4*>(&rb[4]);
                const float* wp = &sm.wdp[sm.r0[pr]][c];
                float df = bdpc
                    + rv0.x * wp[0 * CZ] + rv0.y * wp[1 * CZ]
                    + rv0.z * wp[2 * CZ] + rv0.w * wp[3 * CZ]
                    + rv1.x * wp[4 * CZ] + rv1.y * wp[5 * CZ]
                    + rv1.z * wp[6 * CZ] + rv1.w * wp[7 * CZ];
                updp[jj] += sigmoidf_(gate) * df * e2k;
            }
        }

        // prefetch Wout chunk 0 (regs only; hidden under LN)
        float4 pw4 = *reinterpret_cast<const float4*>(&Wout[wr * CZ + wc4]);

        // 4 groups write disjoint rows — covers all 16
#pragma unroll
        for (int jj = 0; jj < 4; jj++) sm.zu[jb + jj][c] = updp[jj];
        __syncthreads();

        // LayerNorm(upd) in place: warp w -> row w
        {
            float v[4];
#pragma unroll
            for (int i = 0; i < 4; i++) v[i] = sm.zu[w][lane + 32 * i];
            float s = v[0] + v[1] + v[2] + v[3];
            float ss = v[0] * v[0] + v[1] * v[1] + v[2] * v[2] + v[3] * v[3];
#pragma unroll
            for (int off = 16; off; off >>= 1) {
                s  += __shfl_xor_sync(0xffffffffu, s, off);
                ss += __shfl_xor_sync(0xffffffffu, ss, off);
            }
            float m = s * (1.f / 128.f);
            float var = ss * (1.f / 128.f) - m * m;
            float inv = rsqrtf(var + 1e-5f);
            __syncwarp();
#pragma unroll
            for (int i = 0; i < 4; i++) {
                int cc = lane + 32 * i;
                sm.zu[w][cc] = (v[i] - m) * inv * lno_g[cc] + lno_b[cc];
            }
        }
        __syncthreads();

        // out = (LN(upd)@Wout + bout) * gz * mk[j], Wout staged via u48 halves
        {
            float acc[4] = {0.f, 0.f, 0.f, 0.f};
#pragma unroll 1
            for (int ci = 0; ci < 8; ci++) {
                float* wb = sm.u48 + (ci & 1) * 2048;
                reinterpret_cast<float4*>(wb)[t] = pw4;
                __syncthreads();
                if (ci < 7) {
                    int r = (ci + 1) * 16 + wr;
                    pw4 = *reinterpret_cast<const float4*>(&Wout[r * CZ + wc4]);
                }
#pragma unroll
                for (int ii = 0; ii < 16; ii += 4) {
                    float w0 = wb[(ii + 0) * CZ + c], w1 = wb[(ii + 1) * CZ + c];
                    float w2 = wb[(ii + 2) * CZ + c], w3 = wb[(ii + 3) * CZ + c];
                    const int ib = ci * 16 + ii;
#pragma unroll
                    for (int jj = 0; jj < 4; jj++) {
                        float4 z4 = *reinterpret_cast<const float4*>(&sm.zu[jb + jj][ib]);
                        acc[jj] += z4.x * w0 + z4.y * w1 + z4.z * w2 + z4.w * w3;
                    }
                }
            }
            float bo = bout[c];
#pragma unroll
            for (int jj = 0; jj < 4; jj++) {
                int j = jb + jj;
                out[((size_t)n * KNB + j) * CZ + c] = (acc[jj] + bo) * gzr[jj] * sm.mk[j];
            }
        }
    }
}

extern "C" void kernel_launch(void* const* d_in, const int* in_sizes, int n_in,
                              void* d_out, int out_size) {
    const float* node_features = (const float*)d_in[0];
    const float* trans         = (const float*)d_in[1];
    const float* edge_features = (const float*)d_in[2];
    const float* ln_g  = (const float*)d_in[3];
    const float* ln_b  = (const float*)d_in[4];
    const float* Wl    = (const float*)d_in[5];
    const float* bl    = (const float*)d_in[6];
    const float* Wr    = (const float*)d_in[7];
    const float* br    = (const float*)d_in[8];
    const float* Wep   = (const float*)d_in[9];
    const float* bep   = (const float*)d_in[10];
    const float* Weg   = (const float*)d_in[11];
    const float* beg   = (const float*)d_in[12];
    const float* Wdg   = (const float*)d_in[13];
    const float* bdg   = (const float*)d_in[14];
    const float* Wdp   = (const float*)d_in[15];
    const float* bdp   = (const float*)d_in[16];
    const float* lno_g = (const float*)d_in[17];
    const float* lno_b = (const float*)d_in[18];
    const float* Wout  = (const float*)d_in[19];
    const float* bout  = (const float*)d_in[20];
    const float* Wog   = (const float*)d_in[21];
    const float* bog   = (const float*)d_in[22];
    const void* edge_index = d_in[23];
    const void* res_mask   = d_in[25];

    float* outp = (float*)d_out;

    static_assert(sizeof(TriSmem) < 112 * 1024, "smem too big for 2 CTAs");
    cudaFuncSetAttribute(tri_kernel, cudaFuncAttributeMaxDynamicSharedMemorySize,
                         (int)sizeof(TriSmem));

    node_proj_kernel<<<N_NODES, 256>>>(node_features, Wl, bl, Wr, br);
    tt_kernel<<<N_NODES, 256>>>(Wdg);
    tri_kernel<<<TRI_GRID, 512, sizeof(TriSmem)>>>(trans, edge_features, ln_g, ln_b,
                                 Wep, bep, Weg, beg, bdg, Wdp, bdp,
                                 lno_g, lno_b, Wout, bout, Wog, bog,
                                 edge_index, res_mask, outp);
}

// round 17
// speedup vs baseline: 1.1730x; 1.1730x over previous
#include <cuda_runtime.h>
#include <cuda_bf16.h>
#include <math.h>

#define N_NODES 1024
#define KNB 16
#define CZ 128
#define CG 16
#define CS 256
#define NRBF 64
#define TRI_GRID 296   // 2 CTAs x 148 SMs, persistent

// scratch (no cudaMalloc allowed)
__device__ float g_nl[N_NODES * CG];
__device__ float g_nr[N_NODES * CG];
__device__ float g_tt[N_NODES * CG * CZ];   // TT[s][p][c] — coalesced across c

// sigmoid(x) = 0.5*tanh(x/2) + 0.5  (MUFU.TANH: 1 op vs EX2+RCP chain)
__device__ __forceinline__ float sigmoidf_(float x) {
    float th;
    asm("tanh.approx.f32 %0, %1;" : "=f"(th) : "f"(x * 0.5f));
    return fmaf(th, 0.5f, 0.5f);
}

// --- input-encoding sniffers ---
__device__ __forceinline__ bool eidx_is_i64(const void* e) {
    const long long* e64 = (const long long*)e;
    bool is64 = true;
#pragma unroll
    for (int i = 0; i < 4; i++)
        if ((unsigned long long)e64[i] >= 1024ull) is64 = false;
    return is64;
}
__device__ __forceinline__ int load_idx(const void* e, bool is64, int idx) {
    return is64 ? (int)((const long long*)e)[idx] : ((const int*)e)[idx];
}
__device__ __forceinline__ bool mask_true(const void* rm, int s) {
    const unsigned int w0 = ((const unsigned int*)rm)[0];
    const unsigned int w1 = ((const unsigned int*)rm)[1];
    if (w0 == 0x3F800000u) return ((const float*)rm)[s] != 0.0f;
    if ((w0 & 0xFFFFFF00u) != 0u) return ((const unsigned char*)rm)[s] != 0;
    const unsigned int w3 = ((const unsigned int*)rm)[3];
    if (w1 == 0u && w3 == 0u) return ((const long long*)rm)[s] != 0;
    return ((const int*)rm)[s] != 0;
}

// nl = nf @ Wl + bl ; nr = nf @ Wr + br
__global__ __launch_bounds__(256)
void node_proj_kernel(const float* __restrict__ nf,
                      const float* __restrict__ Wl, const float* __restrict__ bl,
                      const float* __restrict__ Wr, const float* __restrict__ br) {
    __shared__ float x[CS];
    const int n = blockIdx.x, t = threadIdx.x;
    x[t] = nf[n * CS + t];
    __syncthreads();
    const int o = t >> 3, l8 = t & 7;
    const int cc = o & 15, sel = o >> 4;
    const float* W = sel ? Wr : Wl;
    float s = 0.f;
    for (int i = l8; i < CS; i += 8) s += x[i] * W[i * CG + cc];
#pragma unroll
    for (int off = 4; off; off >>= 1) s += __shfl_down_sync(0xffffffffu, s, off, 8);
    if (l8 == 0) {
        float bias = sel ? br[cc] : bl[cc];
        (sel ? g_nr : g_nl)[n * CG + cc] = s + bias;
    }
}

// TT[s][p][c] = sum_q nr[s][q] * Wdg[(p*16+q)][c]
__global__ __launch_bounds__(256)
void tt_kernel(const float* __restrict__ Wdg) {
    __shared__ float bq[CG];
    const int s = blockIdx.x, t = threadIdx.x;
    if (t < CG) bq[t] = g_nr[s * CG + t];
    __syncthreads();
    const int c = t & 127, ph = t >> 7;
    float bl_[CG];
#pragma unroll
    for (int q = 0; q < CG; q++) bl_[q] = bq[q];
#pragma unroll
    for (int pp = 0; pp < 8; pp++) {
        int p = ph * 8 + pp;
        float acc = 0.f;
#pragma unroll
        for (int q = 0; q < CG; q++)
            acc += bl_[q] * Wdg[(p * CG + q) * CZ + c];
        g_tt[((size_t)s * CG + p) * CZ + c] = acc;
    }
}

struct __align__(16) TriSmem {
    float zu[KNB][CZ];        // 8KB: z (LN'd), later upd
    float e2s[KNB][CZ];       // 8KB
    float wdp[NRBF][CZ];      // 32KB Wdp table
    float tts[2][2][CG * CZ]; // 32KB: [stage parity][k of pair][plane]
    float rbf[256][8];        // 8KB
    int   r0[256];
    float a[KNB][CG];
    float tp[KNB][4];
    int   src[KNB];
    float mk[KNB];
};

// 512 threads, persistent: thread (c, g) owns 4 output rows jb=g*4 .. jb+3
__global__ __launch_bounds__(512, 2)
void tri_kernel(const float* __restrict__ trans,
                const float* __restrict__ ef,
                const float* __restrict__ ln_g,  const float* __restrict__ ln_b,
                const float* __restrict__ Wep,   const float* __restrict__ bep,
                const float* __restrict__ Weg,   const float* __restrict__ beg,
                const float* __restrict__ bdg,
                const float* __restrict__ Wdp,   const float* __restrict__ bdp,
                const float* __restrict__ lno_g, const float* __restrict__ lno_b,
                const float* __restrict__ Wout,  const float* __restrict__ bout,
                const float* __restrict__ Wog,   const float* __restrict__ bog,
                const void* __restrict__ eidx,
                const void* __restrict__ res_mask,
                float* __restrict__ out) {
    extern __shared__ char smem_raw[];
    TriSmem& sm = *reinterpret_cast<TriSmem*>(smem_raw);

    const int t = threadIdx.x;
    const int lane = t & 31, w = t >> 5;   // 16 warps
    const int c = t & 127, g = t >> 7;     // g in [0,4)
    const int jb = g * 4;
    const bool is64 = eidx_is_i64(eidx);

    // Wdp -> smem, once per CTA
    {
        const float4* src4 = reinterpret_cast<const float4*>(Wdp);
        float4* dst4 = reinterpret_cast<float4*>(&sm.wdp[0][0]);
#pragma unroll
        for (int i = 0; i < 4; i++) dst4[t + 512 * i] = src4[t + 512 * i];
    }

    for (int n = blockIdx.x; n < N_NODES; n += TRI_GRID) {
        __syncthreads();   // protect smem reuse across node iterations

        if (t < KNB) {
            int s = load_idx(eidx, is64, n * KNB + t);
            sm.src[t] = s;
            sm.mk[t] = (mask_true(res_mask, s) && mask_true(res_mask, n)) ? 1.f : 0.f;
        }
        __syncthreads();

        // a = nl[src], neighbor positions (first 256 threads)
        if (t < 256) {
            int k = t >> 4, p = t & 15;
            int s = sm.src[k];
            sm.a[k][p] = g_nl[s * CG + p];
            if (p < 3) sm.tp[k][p] = trans[s * 3 + p];
        }

        // early prefetch: TT planes k=0,1 (hidden under LN/e2/rbf)
        float4 pf0 = reinterpret_cast<const float4*>(
            &g_tt[(size_t)sm.src[0] * (CG * CZ)])[t];
        float4 pf1 = reinterpret_cast<const float4*>(
            &g_tt[(size_t)sm.src[1] * (CG * CZ)])[t];

        // z = LayerNorm(edge rows): warp w -> row w
        {
            const float* row = ef + ((size_t)n * KNB + w) * CZ;
            float v[4];
#pragma unroll
            for (int i = 0; i < 4; i++) v[i] = row[lane + 32 * i];
            float s = v[0] + v[1] + v[2] + v[3];
            float ss = v[0] * v[0] + v[1] * v[1] + v[2] * v[2] + v[3] * v[3];
#pragma unroll
            for (int off = 16; off; off >>= 1) {
                s  += __shfl_xor_sync(0xffffffffu, s, off);
                ss += __shfl_xor_sync(0xffffffffu, ss, off);
            }
            float m = s * (1.f / 128.f);
            float var = ss * (1.f / 128.f) - m * m;
            float inv = rsqrtf(var + 1e-5f);
#pragma unroll
            for (int i = 0; i < 4; i++) {
                int cc = lane + 32 * i;
                sm.zu[w][cc] = (v[i] - m) * inv * ln_g[cc] + ln_b[cc];
            }
        }
        __syncthreads();

        // e2 = sigmoid(z@Weg+beg)*(z@Wep+bep) (mk folded); gz in registers
        float gzr[4];
        {
            float aP[4] = {0.f, 0.f, 0.f, 0.f};
            float aG[4] = {0.f, 0.f, 0.f, 0.f};
            float aO[4] = {0.f, 0.f, 0.f, 0.f};
#pragma unroll 1
            for (int i0 = 0; i0 < CZ; i0 += 4) {
                float wp0 = Wep[(i0 + 0) * CZ + c], wp1 = Wep[(i0 + 1) * CZ + c];
                float wp2 = Wep[(i0 + 2) * CZ + c], wp3 = Wep[(i0 + 3) * CZ + c];
                float wg0 = Weg[(i0 + 0) * CZ + c], wg1 = Weg[(i0 + 1) * CZ + c];
                float wg2 = Weg[(i0 + 2) * CZ + c], wg3 = Weg[(i0 + 3) * CZ + c];
                float wo0 = Wog[(i0 + 0) * CZ + c], wo1 = Wog[(i0 + 1) * CZ + c];
                float wo2 = Wog[(i0 + 2) * CZ + c], wo3 = Wog[(i0 + 3) * CZ + c];
#pragma unroll
                for (int jj = 0; jj < 4; jj++) {
                    float4 z4 = *reinterpret_cast<const float4*>(&sm.zu[jb + jj][i0]);
                    aP[jj] += z4.x * wp0 + z4.y * wp1 + z4.z * wp2 + z4.w * wp3;
                    aG[jj] += z4.x * wg0 + z4.y * wg1 + z4.z * wg2 + z4.w * wg3;
                    aO[jj] += z4.x * wo0 + z4.y * wo1 + z4.z * wo2 + z4.w * wo3;
                }
            }
            float bp = bep[c], bg = beg[c], bo = bog[c];
#pragma unroll
            for (int jj = 0; jj < 4; jj++) {
                int k = jb + jj;
                sm.e2s[k][c] = sigmoidf_(aG[jj] + bg) * (aP[jj] + bp) * sm.mk[k];
                gzr[jj] = sigmoidf_(aO[jj] + bo);
            }
        }

        // RBF windows per pair (first 256 threads), 8 taps
        if (t < 256) {
            int j = t >> 4, k = t & 15;
            float dx = sm.tp[j][0] - sm.tp[k][0] + 1e-8f;
            float dy = sm.tp[j][1] - sm.tp[k][1] + 1e-8f;
            float dz = sm.tp[j][2] - sm.tp[k][2] + 1e-8f;
            float d = sqrtf(dx * dx + dy * dy + dz * dz);
            const float STEP = 20.f / 63.f;
            const float INVS = 1.f / 0.3125f;
            int r0 = (int)floorf(d * (63.f / 20.f)) - 3;
            r0 = r0 < 0 ? 0 : (r0 > 56 ? 56 : r0);
#pragma unroll
            for (int i = 0; i < 8; i++) {
                float mu = (float)(r0 + i) * STEP;
                float x = (d - mu) * INVS;
                sm.rbf[t][i] = __expf(-x * x);
            }
            sm.r0[t] = r0;
        }
        __syncthreads();

        // contraction: 2 TT planes per stage, 8 barriers; one k computed at a
        // time reusing the same ttc registers (64-reg budget)
        float updp[4] = {0.f, 0.f, 0.f, 0.f};
        const float bdgc = bdg[c], bdpc = bdp[c];

#pragma unroll 1
        for (int kp = 0; kp < 8; kp++) {
            const int k0 = 2 * kp;
            float* b0 = sm.tts[kp & 1][0];
            float* b1 = sm.tts[kp & 1][1];
            reinterpret_cast<float4*>(b0)[t] = pf0;
            reinterpret_cast<float4*>(b1)[t] = pf1;
            __syncthreads();
            if (kp < 7) {
                pf0 = reinterpret_cast<const float4*>(
                    &g_tt[(size_t)sm.src[k0 + 2] * (CG * CZ)])[t];
                pf1 = reinterpret_cast<const float4*>(
                    &g_tt[(size_t)sm.src[k0 + 3] * (CG * CZ)])[t];
            }
#pragma unroll
            for (int dk = 0; dk < 2; dk++) {
                const int k = k0 + dk;
                const float* buf = dk ? b1 : b0;
                float ttc[16];
#pragma unroll
                for (int p = 0; p < 16; p++) ttc[p] = buf[p * CZ + c];
                const float e2k = sm.e2s[k][c];
#pragma unroll
                for (int jj = 0; jj < 4; jj++) {
                    const int j = jb + jj;
                    float4 a0 = *reinterpret_cast<const float4*>(&sm.a[j][0]);
                    float4 a1 = *reinterpret_cast<const float4*>(&sm.a[j][4]);
                    float4 a2 = *reinterpret_cast<const float4*>(&sm.a[j][8]);
                    float4 a3 = *reinterpret_cast<const float4*>(&sm.a[j][12]);
                    float gate = bdgc
                        + a0.x * ttc[0]  + a0.y * ttc[1]  + a0.z * ttc[2]  + a0.w * ttc[3]
                        + a1.x * ttc[4]  + a1.y * ttc[5]  + a1.z * ttc[6]  + a1.w * ttc[7]
                        + a2.x * ttc[8]  + a2.y * ttc[9]  + a2.z * ttc[10] + a2.w * ttc[11]
                        + a3.x * ttc[12] + a3.y * ttc[13] + a3.z * ttc[14] + a3.w * ttc[15];
                    const int pr = j * 16 + k;
                    float4 rv0 = *reinterpret_cast<const float4*>(&sm.rbf[pr][0]);
                    float4 rv1 = *reinterpret_cast<const float4*>(&sm.rbf[pr][4]);
                    const float* wp = &sm.wdp[sm.r0[pr]][c];
                    float df = bdpc
                        + rv0.x * wp[0 * CZ] + rv0.y * wp[1 * CZ]
                        + rv0.z * wp[2 * CZ] + rv0.w * wp[3 * CZ]
                        + rv1.x * wp[4 * CZ] + rv1.y * wp[5 * CZ]
                        + rv1.z * wp[6 * CZ] + rv1.w * wp[7 * CZ];
                    updp[jj] += sigmoidf_(gate) * df * e2k;
                }
            }
        }

        // 4 groups write disjoint rows — covers all 16
#pragma unroll
        for (int jj = 0; jj < 4; jj++) sm.zu[jb + jj][c] = updp[jj];
        __syncthreads();

        // LayerNorm(upd) in place: warp w -> row w
        {
            float v[4];
#pragma unroll
            for (int i = 0; i < 4; i++) v[i] = sm.zu[w][lane + 32 * i];
            float s = v[0] + v[1] + v[2] + v[3];
            float ss = v[0] * v[0] + v[1] * v[1] + v[2] * v[2] + v[3] * v[3];
#pragma unroll
            for (int off = 16; off; off >>= 1) {
                s  += __shfl_xor_sync(0xffffffffu, s, off);
                ss += __shfl_xor_sync(0xffffffffu, ss, off);
            }
            float m = s * (1.f / 128.f);
            float var = ss * (1.f / 128.f) - m * m;
            float inv = rsqrtf(var + 1e-5f);
            __syncwarp();
#pragma unroll
            for (int i = 0; i < 4; i++) {
                int cc = lane + 32 * i;
                sm.zu[w][cc] = (v[i] - m) * inv * lno_g[cc] + lno_b[cc];
            }
        }
        __syncthreads();

        // out = (LN(upd)@Wout + bout) * gz * mk[j]  (4 rows per thread)
        {
            float acc[4] = {0.f, 0.f, 0.f, 0.f};
#pragma unroll 1
            for (int i0 = 0; i0 < CZ; i0 += 4) {
                float w0 = Wout[(i0 + 0) * CZ + c], w1 = Wout[(i0 + 1) * CZ + c];
                float w2 = Wout[(i0 + 2) * CZ + c], w3 = Wout[(i0 + 3) * CZ + c];
#pragma unroll
                for (int jj = 0; jj < 4; jj++) {
                    float4 z4 = *reinterpret_cast<const float4*>(&sm.zu[jb + jj][i0]);
                    acc[jj] += z4.x * w0 + z4.y * w1 + z4.z * w2 + z4.w * w3;
                }
            }
            float bo = bout[c];
#pragma unroll
            for (int jj = 0; jj < 4; jj++) {
                int j = jb + jj;
                out[((size_t)n * KNB + j) * CZ + c] = (acc[jj] + bo) * gzr[jj] * sm.mk[j];
            }
        }
    }
}

extern "C" void kernel_launch(void* const* d_in, const int* in_sizes, int n_in,
                              void* d_out, int out_size) {
    const float* node_features = (const float*)d_in[0];
    const float* trans         = (const float*)d_in[1];
    const float* edge_features = (const float*)d_in[2];
    const float* ln_g  = (const float*)d_in[3];
    const float* ln_b  = (const float*)d_in[4];
    const float* Wl    = (const float*)d_in[5];
    const float* bl    = (const float*)d_in[6];
    const float* Wr    = (const float*)d_in[7];
    const float* br    = (const float*)d_in[8];
    const float* Wep   = (const float*)d_in[9];
    const float* bep   = (const float*)d_in[10];
    const float* Weg   = (const float*)d_in[11];
    const float* beg   = (const float*)d_in[12];
    const float* Wdg   = (const float*)d_in[13];
    const float* bdg   = (const float*)d_in[14];
    const float* Wdp   = (const float*)d_in[15];
    const float* bdp   = (const float*)d_in[16];
    const float* lno_g = (const float*)d_in[17];
    const float* lno_b = (const float*)d_in[18];
    const float* Wout  = (const float*)d_in[19];
    const float* bout  = (const float*)d_in[20];
    const float* Wog   = (const float*)d_in[21];
    const float* bog   = (const float*)d_in[22];
    const void* edge_index = d_in[23];
    const void* res_mask   = d_in[25];

    float* outp = (float*)d_out;

    static_assert(sizeof(TriSmem) < 112 * 1024, "smem too big for 2 CTAs");
    cudaFuncSetAttribute(tri_kernel, cudaFuncAttributeMaxDynamicSharedMemorySize,
                         (int)sizeof(TriSmem));

    node_proj_kernel<<<N_NODES, 256>>>(node_features, Wl, bl, Wr, br);
    tt_kernel<<<N_NODES, 256>>>(Wdg);
    tri_kernel<<<TRI_GRID, 512, sizeof(TriSmem)>>>(trans, edge_features, ln_g, ln_b,
                                 Wep, bep, Weg, beg, bdg, Wdp, bdp,
                                 lno_g, lno_b, Wout, bout, Wog, bog,
                                 edge_index, res_mask, outp);
}